// round 6
// baseline (speedup 1.0000x reference)
#include <cuda_runtime.h>
#include <cuda_bf16.h>
#include <cstdint>

// RankOnePlanes, HMMA bf16-split path, round 6.
// R5 showed nothing saturated (tensor 41 / L1 59 / issue 48 / occ 21.7):
// latency-bound with only 16 warps/SM. This round: 512-thread CTAs,
// __launch_bounds__(512,3) -> 3 CTAs/SM (224.3 KB smem of 228) = 48 warps/SM.
// Per-warp algorithm unchanged from R5 (register-built A fragments,
// quarter-block table layout, 6-MMA split-bf16, fused epilogue).

#define LTAB 128
#define CL 32
#define HDIM 128
#define TSTRIDE 36   // floats per table row (4 x 32B quarter-blocks + 16B pad)
#define NTHREADS 512
#define WARPS_PER_CTA 16
#define NBLOCKS 456  // 3 per SM on 152-SM GB300
#define ROWPAD 144   // W1 row bytes (64 bf16 + 16B pad)

// ---- smem byte offsets ----
#define SM_TAB 0                          // 3*128*36*4 = 55296
#define SM_W1  55296                      // 128 * 144  = 18432
#define SM_B1  (55296 + 18432)            // 512
#define SM_W2  (SM_B1 + 512)              // 512
#define SMEM_BYTES (SM_W2 + 512)          // 74752

__device__ __forceinline__ uint32_t smem_u32(const void* p) {
    uint32_t a;
    asm("{ .reg .u64 t; cvta.to.shared.u64 t, %1; cvt.u32.u64 %0, t; }"
        : "=r"(a) : "l"(p));
    return a;
}
__device__ __forceinline__ void ldsm_x4(uint32_t addr, uint32_t* r) {
    asm volatile("ldmatrix.sync.aligned.m8n8.x4.shared.b16 {%0,%1,%2,%3}, [%4];"
                 : "=r"(r[0]), "=r"(r[1]), "=r"(r[2]), "=r"(r[3]) : "r"(addr));
}
__device__ __forceinline__ void mma_bf16(float4& c, const uint32_t* a,
                                         const uint32_t* b) {
    asm volatile(
        "mma.sync.aligned.m16n8k16.row.col.f32.bf16.bf16.f32 "
        "{%0,%1,%2,%3}, {%4,%5,%6,%7}, {%8,%9}, {%0,%1,%2,%3};"
        : "+f"(c.x), "+f"(c.y), "+f"(c.z), "+f"(c.w)
        : "r"(a[0]), "r"(a[1]), "r"(a[2]), "r"(a[3]), "r"(b[0]), "r"(b[1]));
}
__device__ __forceinline__ uint32_t pkbf(float a, float b) {
    __nv_bfloat162 t = __floats2bfloat162_rn(a, b);
    return *reinterpret_cast<uint32_t*>(&t);
}

__device__ __forceinline__ void sample_setup(float c, int& r0, int& r1,
                                             float& w0, float& w1) {
    float pos = (c + 1.0f) * 63.5f;
    float f0  = floorf(pos);
    float fr  = pos - f0;
    int i0 = (int)f0;
    int i1 = i0 + 1;
    w0 = ((unsigned)i0 < (unsigned)LTAB) ? (1.0f - fr) : 0.0f;
    w1 = ((unsigned)i1 < (unsigned)LTAB) ? fr : 0.0f;
    r0 = min(max(i0, 0), LTAB - 1);
    r1 = min(max(i1, 0), LTAB - 1);
}

// 8 features (this lane's quarter-block channels) for one point.
__device__ __forceinline__ void feats8(const float* __restrict__ sT, int qoff,
                                       float cx, float cy, float cz,
                                       float* __restrict__ f) {
    int xr0, xr1, yr0, yr1, zr0, zr1;
    float xw0, xw1, yw0, yw1, zw0, zw1;
    sample_setup(cx, xr0, xr1, xw0, xw1);
    sample_setup(cy, yr0, yr1, yw0, yw1);
    sample_setup(cz, zr0, zr1, zw0, zw1);

    const float4* X0 = reinterpret_cast<const float4*>(&sT[(0 * LTAB + xr0) * TSTRIDE + qoff]);
    const float4* X1 = reinterpret_cast<const float4*>(&sT[(0 * LTAB + xr1) * TSTRIDE + qoff]);
    const float4* Y0 = reinterpret_cast<const float4*>(&sT[(1 * LTAB + yr0) * TSTRIDE + qoff]);
    const float4* Y1 = reinterpret_cast<const float4*>(&sT[(1 * LTAB + yr1) * TSTRIDE + qoff]);
    const float4* Z0 = reinterpret_cast<const float4*>(&sT[(2 * LTAB + zr0) * TSTRIDE + qoff]);
    const float4* Z1 = reinterpret_cast<const float4*>(&sT[(2 * LTAB + zr1) * TSTRIDE + qoff]);

    const float invR  = 2.5f;
    const float invR2 = 6.25f;

#define FEAT1(OUT, X0v, X1v, Y0v, Y1v, Z0v, Z1v)            \
    {                                                       \
        float xv = fmaf((X1v), xw1, (X0v) * xw0);           \
        float yv = fmaf((Y1v), yw1, (Y0v) * yw0);           \
        float zv = fmaf((Z1v), zw1, (Z0v) * zw0);           \
        float s  = xv + yv + zv;                            \
        float xy = xv * yv;                                 \
        float p2 = fmaf(xv, zv, xy);                        \
        p2 = fmaf(yv, zv, p2);                              \
        float p3 = xy * zv;                                 \
        float fv = fmaf(p2, invR, s);                       \
        OUT = fmaf(p3, invR2, fv);                          \
    }
#pragma unroll
    for (int hlf = 0; hlf < 2; hlf++) {
        float4 xa0 = X0[hlf], xa1 = X1[hlf];
        float4 ya0 = Y0[hlf], ya1 = Y1[hlf];
        float4 za0 = Z0[hlf], za1 = Z1[hlf];
        FEAT1(f[4 * hlf + 0], xa0.x, xa1.x, ya0.x, ya1.x, za0.x, za1.x);
        FEAT1(f[4 * hlf + 1], xa0.y, xa1.y, ya0.y, ya1.y, za0.y, za1.y);
        FEAT1(f[4 * hlf + 2], xa0.z, xa1.z, ya0.z, ya1.z, za0.z, za1.z);
        FEAT1(f[4 * hlf + 3], xa0.w, xa1.w, ya0.w, ya1.w, za0.w, za1.w);
    }
#undef FEAT1
}

__global__ __launch_bounds__(NTHREADS, 3)
void rank1_hmma_kernel(const float* __restrict__ coords,
                       const float* __restrict__ lines,
                       const float* __restrict__ W1,
                       const float* __restrict__ b1,
                       const float* __restrict__ W2,
                       const float* __restrict__ b2,
                       float* __restrict__ out, int M) {
    extern __shared__ char smc[];
    const uint32_t sb = smem_u32(smc);
    float* sT  = reinterpret_cast<float*>(smc + SM_TAB);
    float* sb1 = reinterpret_cast<float*>(smc + SM_B1);
    float* sW2 = reinterpret_cast<float*>(smc + SM_W2);

    const int tid  = threadIdx.x;
    const int wid  = tid >> 5;
    const int lane = tid & 31;

    // ---- stage table: per row, 4 quarter-blocks of 8 permuted channels ----
    // block q holds channels {2q,2q+1,2q+8,2q+9,2q+16,2q+17,2q+24,2q+25}
    for (int idx = tid; idx < 3 * LTAB; idx += NTHREADS) {
        const float* src = lines + idx * CL;
        float v[CL];
#pragma unroll
        for (int j = 0; j < 8; j++) {
            float4 t4 = reinterpret_cast<const float4*>(src)[j];
            v[4 * j + 0] = t4.x; v[4 * j + 1] = t4.y;
            v[4 * j + 2] = t4.z; v[4 * j + 3] = t4.w;
        }
        float* dst = sT + idx * TSTRIDE;
#pragma unroll
        for (int q = 0; q < 4; q++) {
            dst[8 * q + 0] = v[2 * q];      dst[8 * q + 1] = v[2 * q + 1];
            dst[8 * q + 2] = v[2 * q + 8];  dst[8 * q + 3] = v[2 * q + 9];
            dst[8 * q + 4] = v[2 * q + 16]; dst[8 * q + 5] = v[2 * q + 17];
            dst[8 * q + 6] = v[2 * q + 24]; dst[8 * q + 7] = v[2 * q + 25];
        }
    }
    // ---- stage b1, W2, split-bf16 W1 = [wh | wl] (channel order identity) ----
    if (tid < HDIM) {
        sb1[tid] = b1[tid];
        sW2[tid] = W2[tid];
        char* dst = smc + SM_W1 + tid * ROWPAD;
        const float4* wrow = reinterpret_cast<const float4*>(W1 + tid * CL);
#pragma unroll
        for (int j = 0; j < 8; j += 2) {
            float4 wa = wrow[j], wb = wrow[j + 1];
            float ha0 = __bfloat162float(__float2bfloat16(wa.x));
            float ha1 = __bfloat162float(__float2bfloat16(wa.y));
            float ha2 = __bfloat162float(__float2bfloat16(wa.z));
            float ha3 = __bfloat162float(__float2bfloat16(wa.w));
            float hb0 = __bfloat162float(__float2bfloat16(wb.x));
            float hb1 = __bfloat162float(__float2bfloat16(wb.y));
            float hb2 = __bfloat162float(__float2bfloat16(wb.z));
            float hb3 = __bfloat162float(__float2bfloat16(wb.w));
            uint4 vh = make_uint4(pkbf(ha0, ha1), pkbf(ha2, ha3),
                                  pkbf(hb0, hb1), pkbf(hb2, hb3));
            uint4 vl = make_uint4(pkbf(wa.x - ha0, wa.y - ha1),
                                  pkbf(wa.z - ha2, wa.w - ha3),
                                  pkbf(wb.x - hb0, wb.y - hb1),
                                  pkbf(wb.z - hb2, wb.w - hb3));
            *reinterpret_cast<uint4*>(dst + j * 8)      = vh;
            *reinterpret_cast<uint4*>(dst + 64 + j * 8) = vl;
        }
    }
    __syncthreads();

    const float bias2 = __ldg(b2);
    const uint32_t sbW1 = sb + SM_W1;

    // B ldmatrix addressing
    const uint32_t b_row = (uint32_t)((lane & 7) + ((lane & 16) ? 8 : 0));
    const uint32_t b_addr_base =
        sbW1 + b_row * ROWPAD + (uint32_t)((lane & 8) ? 16 : 0);

    const int qoff = (lane & 3) * 8;
    const int base = lane >> 2;

    const int warp_gid    = blockIdx.x * WARPS_PER_CTA + wid;
    const int total_warps = NBLOCKS * WARPS_PER_CTA;
    const int tiles       = (M + 31) >> 5;

    for (int t = warp_gid; t < tiles; t += total_warps) {
        // ---- build A fragments in registers: 4 points per lane ----
        uint32_t afr[2][4][4];   // [row-tile][k-chunk][frag reg]
#pragma unroll
        for (int pi = 0; pi < 4; pi++) {
            int prow = base + pi * 8;
            int p  = t * 32 + prow;
            int pc = (p < M) ? p : (M - 1);
            float cx = __ldg(&coords[3 * pc + 0]);
            float cy = __ldg(&coords[3 * pc + 1]);
            float cz = __ldg(&coords[3 * pc + 2]);
            float f[8];
            feats8(sT, qoff, cx, cy, cz, f);

            float h[8], l[8];
#pragma unroll
            for (int u = 0; u < 8; u++) {
                h[u] = __bfloat162float(__float2bfloat16(f[u]));
                l[u] = f[u] - h[u];
            }
            int rt = pi >> 1;
            int rs = pi & 1;
            afr[rt][0][rs]     = pkbf(h[0], h[1]);
            afr[rt][0][2 + rs] = pkbf(h[2], h[3]);
            afr[rt][1][rs]     = pkbf(h[4], h[5]);
            afr[rt][1][2 + rs] = pkbf(h[6], h[7]);
            afr[rt][2][rs]     = pkbf(l[0], l[1]);
            afr[rt][2][2 + rs] = pkbf(l[2], l[3]);
            afr[rt][3][rs]     = pkbf(l[4], l[5]);
            afr[rt][3][2 + rs] = pkbf(l[6], l[7]);
        }

        float oacc0 = 0.0f, oacc1 = 0.0f, oacc2 = 0.0f, oacc3 = 0.0f;
        const int colb = (lane & 3) * 2;

#pragma unroll
        for (int np = 0; np < 8; np++) {
            uint32_t b[4][4];  // [k16 chunk][ntile0 b0,b1, ntile1 b0,b1]
#pragma unroll
            for (int kc = 0; kc < 4; kc++)
                ldsm_x4(b_addr_base + (uint32_t)(np * 16) * ROWPAD +
                            (uint32_t)(kc * 32),
                        b[kc]);

            float4 c[2][2];
#pragma unroll
            for (int rt = 0; rt < 2; rt++)
#pragma unroll
                for (int nt = 0; nt < 2; nt++)
                    c[rt][nt] = make_float4(0.f, 0.f, 0.f, 0.f);

#pragma unroll
            for (int rt = 0; rt < 2; rt++) {
#pragma unroll
                for (int nt = 0; nt < 2; nt++) {
                    mma_bf16(c[rt][nt], afr[rt][0], &b[0][nt * 2]);  // fh*wh k0
                    mma_bf16(c[rt][nt], afr[rt][1], &b[1][nt * 2]);  // fh*wh k1
                    mma_bf16(c[rt][nt], afr[rt][0], &b[2][nt * 2]);  // fh*wl k0
                    mma_bf16(c[rt][nt], afr[rt][1], &b[3][nt * 2]);  // fh*wl k1
                    mma_bf16(c[rt][nt], afr[rt][2], &b[0][nt * 2]);  // fl*wh k0
                    mma_bf16(c[rt][nt], afr[rt][3], &b[1][nt * 2]);  // fl*wh k1
                }
            }

            // ---- fused epilogue on fragments ----
            int col0 = np * 16 + colb;
            float2 b1a = *reinterpret_cast<const float2*>(&sb1[col0]);
            float2 w2a = *reinterpret_cast<const float2*>(&sW2[col0]);
            float2 b1b = *reinterpret_cast<const float2*>(&sb1[col0 + 8]);
            float2 w2b = *reinterpret_cast<const float2*>(&sW2[col0 + 8]);
#pragma unroll
            for (int rt = 0; rt < 2; rt++) {
                float lo = 0.0f, hi = 0.0f;
                lo = fmaf(fmaxf(c[rt][0].x + b1a.x, 0.f), w2a.x, lo);
                lo = fmaf(fmaxf(c[rt][0].y + b1a.y, 0.f), w2a.y, lo);
                lo = fmaf(fmaxf(c[rt][1].x + b1b.x, 0.f), w2b.x, lo);
                lo = fmaf(fmaxf(c[rt][1].y + b1b.y, 0.f), w2b.y, lo);
                hi = fmaf(fmaxf(c[rt][0].z + b1a.x, 0.f), w2a.x, hi);
                hi = fmaf(fmaxf(c[rt][0].w + b1a.y, 0.f), w2a.y, hi);
                hi = fmaf(fmaxf(c[rt][1].z + b1b.x, 0.f), w2b.x, hi);
                hi = fmaf(fmaxf(c[rt][1].w + b1b.y, 0.f), w2b.y, hi);
                if (rt == 0) { oacc0 += lo; oacc1 += hi; }
                else         { oacc2 += lo; oacc3 += hi; }
            }
        }

        // ---- reduce over the 4 lanes sharing each row ----
        oacc0 += __shfl_xor_sync(0xffffffffu, oacc0, 1);
        oacc0 += __shfl_xor_sync(0xffffffffu, oacc0, 2);
        oacc1 += __shfl_xor_sync(0xffffffffu, oacc1, 1);
        oacc1 += __shfl_xor_sync(0xffffffffu, oacc1, 2);
        oacc2 += __shfl_xor_sync(0xffffffffu, oacc2, 1);
        oacc2 += __shfl_xor_sync(0xffffffffu, oacc2, 2);
        oacc3 += __shfl_xor_sync(0xffffffffu, oacc3, 1);
        oacc3 += __shfl_xor_sync(0xffffffffu, oacc3, 2);

        if ((lane & 3) == 0) {
            int r  = lane >> 2;
            int pb = t * 32;
            if (pb + r      < M) out[pb + r]      = oacc0 + bias2;
            if (pb + r + 8  < M) out[pb + r + 8]  = oacc1 + bias2;
            if (pb + r + 16 < M) out[pb + r + 16] = oacc2 + bias2;
            if (pb + r + 24 < M) out[pb + r + 24] = oacc3 + bias2;
        }
    }
}

extern "C" void kernel_launch(void* const* d_in, const int* in_sizes, int n_in,
                              void* d_out, int out_size) {
    const float* coords = (const float*)d_in[0];
    const float* lines  = (const float*)d_in[1];
    const float* W1     = (const float*)d_in[2];
    const float* b1     = (const float*)d_in[3];
    const float* W2     = (const float*)d_in[4];
    const float* b2     = (const float*)d_in[5];
    float* out = (float*)d_out;

    int M = in_sizes[0] / 3;

    cudaFuncSetAttribute(rank1_hmma_kernel,
                         cudaFuncAttributeMaxDynamicSharedMemorySize, SMEM_BYTES);

    rank1_hmma_kernel<<<NBLOCKS, NTHREADS, SMEM_BYTES>>>(
        coords, lines, W1, b1, W2, b2, out, M);
}

// round 7
// speedup vs baseline: 4.8807x; 4.8807x over previous
#include <cuda_runtime.h>
#include <cuda_bf16.h>
#include <cstdint>

// RankOnePlanes, HMMA bf16-split path, round 7.
// R6 lesson: 512x3 forced 40 regs -> full spill (DRAM 52%). Register file,
// not smem, is the occupancy limiter: 64K regs/SM / 768 thr = 85 regs.
// This round: identical R5 algorithm, 256-thread CTAs,
// __launch_bounds__(256,3) -> 84 regs, 24 warps/SM (1.5x R5), grid 456.

#define LTAB 128
#define CL 32
#define HDIM 128
#define TSTRIDE 36   // floats per table row (4 x 32B quarter-blocks + 16B pad)
#define NTHREADS 256
#define WARPS_PER_CTA 8
#define NBLOCKS 456  // 3 per SM on 152-SM GB300
#define ROWPAD 144   // W1 row bytes (64 bf16 + 16B pad)

// ---- smem byte offsets ----
#define SM_TAB 0                          // 3*128*36*4 = 55296
#define SM_W1  55296                      // 128 * 144  = 18432
#define SM_B1  (55296 + 18432)            // 512
#define SM_W2  (SM_B1 + 512)              // 512
#define SMEM_BYTES (SM_W2 + 512)          // 74752  (x3 CTAs = 224.3 KB/SM)

__device__ __forceinline__ uint32_t smem_u32(const void* p) {
    uint32_t a;
    asm("{ .reg .u64 t; cvta.to.shared.u64 t, %1; cvt.u32.u64 %0, t; }"
        : "=r"(a) : "l"(p));
    return a;
}
__device__ __forceinline__ void ldsm_x4(uint32_t addr, uint32_t* r) {
    asm volatile("ldmatrix.sync.aligned.m8n8.x4.shared.b16 {%0,%1,%2,%3}, [%4];"
                 : "=r"(r[0]), "=r"(r[1]), "=r"(r[2]), "=r"(r[3]) : "r"(addr));
}
__device__ __forceinline__ void mma_bf16(float4& c, const uint32_t* a,
                                         const uint32_t* b) {
    asm volatile(
        "mma.sync.aligned.m16n8k16.row.col.f32.bf16.bf16.f32 "
        "{%0,%1,%2,%3}, {%4,%5,%6,%7}, {%8,%9}, {%0,%1,%2,%3};"
        : "+f"(c.x), "+f"(c.y), "+f"(c.z), "+f"(c.w)
        : "r"(a[0]), "r"(a[1]), "r"(a[2]), "r"(a[3]), "r"(b[0]), "r"(b[1]));
}
__device__ __forceinline__ uint32_t pkbf(float a, float b) {
    __nv_bfloat162 t = __floats2bfloat162_rn(a, b);
    return *reinterpret_cast<uint32_t*>(&t);
}

__device__ __forceinline__ void sample_setup(float c, int& r0, int& r1,
                                             float& w0, float& w1) {
    float pos = (c + 1.0f) * 63.5f;
    float f0  = floorf(pos);
    float fr  = pos - f0;
    int i0 = (int)f0;
    int i1 = i0 + 1;
    w0 = ((unsigned)i0 < (unsigned)LTAB) ? (1.0f - fr) : 0.0f;
    w1 = ((unsigned)i1 < (unsigned)LTAB) ? fr : 0.0f;
    r0 = min(max(i0, 0), LTAB - 1);
    r1 = min(max(i1, 0), LTAB - 1);
}

// 8 features (this lane's quarter-block channels) for one point.
__device__ __forceinline__ void feats8(const float* __restrict__ sT, int qoff,
                                       float cx, float cy, float cz,
                                       float* __restrict__ f) {
    int xr0, xr1, yr0, yr1, zr0, zr1;
    float xw0, xw1, yw0, yw1, zw0, zw1;
    sample_setup(cx, xr0, xr1, xw0, xw1);
    sample_setup(cy, yr0, yr1, yw0, yw1);
    sample_setup(cz, zr0, zr1, zw0, zw1);

    const float4* X0 = reinterpret_cast<const float4*>(&sT[(0 * LTAB + xr0) * TSTRIDE + qoff]);
    const float4* X1 = reinterpret_cast<const float4*>(&sT[(0 * LTAB + xr1) * TSTRIDE + qoff]);
    const float4* Y0 = reinterpret_cast<const float4*>(&sT[(1 * LTAB + yr0) * TSTRIDE + qoff]);
    const float4* Y1 = reinterpret_cast<const float4*>(&sT[(1 * LTAB + yr1) * TSTRIDE + qoff]);
    const float4* Z0 = reinterpret_cast<const float4*>(&sT[(2 * LTAB + zr0) * TSTRIDE + qoff]);
    const float4* Z1 = reinterpret_cast<const float4*>(&sT[(2 * LTAB + zr1) * TSTRIDE + qoff]);

    const float invR  = 2.5f;
    const float invR2 = 6.25f;

#define FEAT1(OUT, X0v, X1v, Y0v, Y1v, Z0v, Z1v)            \
    {                                                       \
        float xv = fmaf((X1v), xw1, (X0v) * xw0);           \
        float yv = fmaf((Y1v), yw1, (Y0v) * yw0);           \
        float zv = fmaf((Z1v), zw1, (Z0v) * zw0);           \
        float s  = xv + yv + zv;                            \
        float xy = xv * yv;                                 \
        float p2 = fmaf(xv, zv, xy);                        \
        p2 = fmaf(yv, zv, p2);                              \
        float p3 = xy * zv;                                 \
        float fv = fmaf(p2, invR, s);                       \
        OUT = fmaf(p3, invR2, fv);                          \
    }
#pragma unroll
    for (int hlf = 0; hlf < 2; hlf++) {
        float4 xa0 = X0[hlf], xa1 = X1[hlf];
        float4 ya0 = Y0[hlf], ya1 = Y1[hlf];
        float4 za0 = Z0[hlf], za1 = Z1[hlf];
        FEAT1(f[4 * hlf + 0], xa0.x, xa1.x, ya0.x, ya1.x, za0.x, za1.x);
        FEAT1(f[4 * hlf + 1], xa0.y, xa1.y, ya0.y, ya1.y, za0.y, za1.y);
        FEAT1(f[4 * hlf + 2], xa0.z, xa1.z, ya0.z, ya1.z, za0.z, za1.z);
        FEAT1(f[4 * hlf + 3], xa0.w, xa1.w, ya0.w, ya1.w, za0.w, za1.w);
    }
#undef FEAT1
}

__global__ __launch_bounds__(NTHREADS, 3)
void rank1_hmma_kernel(const float* __restrict__ coords,
                       const float* __restrict__ lines,
                       const float* __restrict__ W1,
                       const float* __restrict__ b1,
                       const float* __restrict__ W2,
                       const float* __restrict__ b2,
                       float* __restrict__ out, int M) {
    extern __shared__ char smc[];
    const uint32_t sb = smem_u32(smc);
    float* sT  = reinterpret_cast<float*>(smc + SM_TAB);
    float* sb1 = reinterpret_cast<float*>(smc + SM_B1);
    float* sW2 = reinterpret_cast<float*>(smc + SM_W2);

    const int tid  = threadIdx.x;
    const int wid  = tid >> 5;
    const int lane = tid & 31;

    // ---- stage table: per row, 4 quarter-blocks of 8 permuted channels ----
    // block q holds channels {2q,2q+1,2q+8,2q+9,2q+16,2q+17,2q+24,2q+25}
    for (int idx = tid; idx < 3 * LTAB; idx += NTHREADS) {
        const float* src = lines + idx * CL;
        float v[CL];
#pragma unroll
        for (int j = 0; j < 8; j++) {
            float4 t4 = reinterpret_cast<const float4*>(src)[j];
            v[4 * j + 0] = t4.x; v[4 * j + 1] = t4.y;
            v[4 * j + 2] = t4.z; v[4 * j + 3] = t4.w;
        }
        float* dst = sT + idx * TSTRIDE;
#pragma unroll
        for (int q = 0; q < 4; q++) {
            dst[8 * q + 0] = v[2 * q];      dst[8 * q + 1] = v[2 * q + 1];
            dst[8 * q + 2] = v[2 * q + 8];  dst[8 * q + 3] = v[2 * q + 9];
            dst[8 * q + 4] = v[2 * q + 16]; dst[8 * q + 5] = v[2 * q + 17];
            dst[8 * q + 6] = v[2 * q + 24]; dst[8 * q + 7] = v[2 * q + 25];
        }
    }
    // ---- stage b1, W2, split-bf16 W1 = [wh | wl] (channel order identity) ----
    if (tid < HDIM) {
        sb1[tid] = b1[tid];
        sW2[tid] = W2[tid];
        char* dst = smc + SM_W1 + tid * ROWPAD;
        const float4* wrow = reinterpret_cast<const float4*>(W1 + tid * CL);
#pragma unroll
        for (int j = 0; j < 8; j += 2) {
            float4 wa = wrow[j], wb = wrow[j + 1];
            float ha0 = __bfloat162float(__float2bfloat16(wa.x));
            float ha1 = __bfloat162float(__float2bfloat16(wa.y));
            float ha2 = __bfloat162float(__float2bfloat16(wa.z));
            float ha3 = __bfloat162float(__float2bfloat16(wa.w));
            float hb0 = __bfloat162float(__float2bfloat16(wb.x));
            float hb1 = __bfloat162float(__float2bfloat16(wb.y));
            float hb2 = __bfloat162float(__float2bfloat16(wb.z));
            float hb3 = __bfloat162float(__float2bfloat16(wb.w));
            uint4 vh = make_uint4(pkbf(ha0, ha1), pkbf(ha2, ha3),
                                  pkbf(hb0, hb1), pkbf(hb2, hb3));
            uint4 vl = make_uint4(pkbf(wa.x - ha0, wa.y - ha1),
                                  pkbf(wa.z - ha2, wa.w - ha3),
                                  pkbf(wb.x - hb0, wb.y - hb1),
                                  pkbf(wb.z - hb2, wb.w - hb3));
            *reinterpret_cast<uint4*>(dst + j * 8)      = vh;
            *reinterpret_cast<uint4*>(dst + 64 + j * 8) = vl;
        }
    }
    __syncthreads();

    const float bias2 = __ldg(b2);
    const uint32_t sbW1 = sb + SM_W1;

    // B ldmatrix addressing
    const uint32_t b_row = (uint32_t)((lane & 7) + ((lane & 16) ? 8 : 0));
    const uint32_t b_addr_base =
        sbW1 + b_row * ROWPAD + (uint32_t)((lane & 8) ? 16 : 0);

    const int qoff = (lane & 3) * 8;
    const int base = lane >> 2;

    const int warp_gid    = blockIdx.x * WARPS_PER_CTA + wid;
    const int total_warps = NBLOCKS * WARPS_PER_CTA;
    const int tiles       = (M + 31) >> 5;

    for (int t = warp_gid; t < tiles; t += total_warps) {
        // ---- build A fragments in registers: 4 points per lane ----
        uint32_t afr[2][4][4];   // [row-tile][k-chunk][frag reg]
#pragma unroll
        for (int pi = 0; pi < 4; pi++) {
            int prow = base + pi * 8;
            int p  = t * 32 + prow;
            int pc = (p < M) ? p : (M - 1);
            float cx = __ldg(&coords[3 * pc + 0]);
            float cy = __ldg(&coords[3 * pc + 1]);
            float cz = __ldg(&coords[3 * pc + 2]);
            float f[8];
            feats8(sT, qoff, cx, cy, cz, f);

            float h[8], l[8];
#pragma unroll
            for (int u = 0; u < 8; u++) {
                h[u] = __bfloat162float(__float2bfloat16(f[u]));
                l[u] = f[u] - h[u];
            }
            int rt = pi >> 1;
            int rs = pi & 1;
            afr[rt][0][rs]     = pkbf(h[0], h[1]);
            afr[rt][0][2 + rs] = pkbf(h[2], h[3]);
            afr[rt][1][rs]     = pkbf(h[4], h[5]);
            afr[rt][1][2 + rs] = pkbf(h[6], h[7]);
            afr[rt][2][rs]     = pkbf(l[0], l[1]);
            afr[rt][2][2 + rs] = pkbf(l[2], l[3]);
            afr[rt][3][rs]     = pkbf(l[4], l[5]);
            afr[rt][3][2 + rs] = pkbf(l[6], l[7]);
        }

        float oacc0 = 0.0f, oacc1 = 0.0f, oacc2 = 0.0f, oacc3 = 0.0f;
        const int colb = (lane & 3) * 2;

#pragma unroll
        for (int np = 0; np < 8; np++) {
            uint32_t b[4][4];  // [k16 chunk][ntile0 b0,b1, ntile1 b0,b1]
#pragma unroll
            for (int kc = 0; kc < 4; kc++)
                ldsm_x4(b_addr_base + (uint32_t)(np * 16) * ROWPAD +
                            (uint32_t)(kc * 32),
                        b[kc]);

            float4 c[2][2];
#pragma unroll
            for (int rt = 0; rt < 2; rt++)
#pragma unroll
                for (int nt = 0; nt < 2; nt++)
                    c[rt][nt] = make_float4(0.f, 0.f, 0.f, 0.f);

#pragma unroll
            for (int rt = 0; rt < 2; rt++) {
#pragma unroll
                for (int nt = 0; nt < 2; nt++) {
                    mma_bf16(c[rt][nt], afr[rt][0], &b[0][nt * 2]);  // fh*wh k0
                    mma_bf16(c[rt][nt], afr[rt][1], &b[1][nt * 2]);  // fh*wh k1
                    mma_bf16(c[rt][nt], afr[rt][0], &b[2][nt * 2]);  // fh*wl k0
                    mma_bf16(c[rt][nt], afr[rt][1], &b[3][nt * 2]);  // fh*wl k1
                    mma_bf16(c[rt][nt], afr[rt][2], &b[0][nt * 2]);  // fl*wh k0
                    mma_bf16(c[rt][nt], afr[rt][3], &b[1][nt * 2]);  // fl*wh k1
                }
            }

            // ---- fused epilogue on fragments ----
            int col0 = np * 16 + colb;
            float2 b1a = *reinterpret_cast<const float2*>(&sb1[col0]);
            float2 w2a = *reinterpret_cast<const float2*>(&sW2[col0]);
            float2 b1b = *reinterpret_cast<const float2*>(&sb1[col0 + 8]);
            float2 w2b = *reinterpret_cast<const float2*>(&sW2[col0 + 8]);
#pragma unroll
            for (int rt = 0; rt < 2; rt++) {
                float lo = 0.0f, hi = 0.0f;
                lo = fmaf(fmaxf(c[rt][0].x + b1a.x, 0.f), w2a.x, lo);
                lo = fmaf(fmaxf(c[rt][0].y + b1a.y, 0.f), w2a.y, lo);
                lo = fmaf(fmaxf(c[rt][1].x + b1b.x, 0.f), w2b.x, lo);
                lo = fmaf(fmaxf(c[rt][1].y + b1b.y, 0.f), w2b.y, lo);
                hi = fmaf(fmaxf(c[rt][0].z + b1a.x, 0.f), w2a.x, hi);
                hi = fmaf(fmaxf(c[rt][0].w + b1a.y, 0.f), w2a.y, hi);
                hi = fmaf(fmaxf(c[rt][1].z + b1b.x, 0.f), w2b.x, hi);
                hi = fmaf(fmaxf(c[rt][1].w + b1b.y, 0.f), w2b.y, hi);
                if (rt == 0) { oacc0 += lo; oacc1 += hi; }
                else         { oacc2 += lo; oacc3 += hi; }
            }
        }

        // ---- reduce over the 4 lanes sharing each row ----
        oacc0 += __shfl_xor_sync(0xffffffffu, oacc0, 1);
        oacc0 += __shfl_xor_sync(0xffffffffu, oacc0, 2);
        oacc1 += __shfl_xor_sync(0xffffffffu, oacc1, 1);
        oacc1 += __shfl_xor_sync(0xffffffffu, oacc1, 2);
        oacc2 += __shfl_xor_sync(0xffffffffu, oacc2, 1);
        oacc2 += __shfl_xor_sync(0xffffffffu, oacc2, 2);
        oacc3 += __shfl_xor_sync(0xffffffffu, oacc3, 1);
        oacc3 += __shfl_xor_sync(0xffffffffu, oacc3, 2);

        if ((lane & 3) == 0) {
            int r  = lane >> 2;
            int pb = t * 32;
            if (pb + r      < M) out[pb + r]      = oacc0 + bias2;
            if (pb + r + 8  < M) out[pb + r + 8]  = oacc1 + bias2;
            if (pb + r + 16 < M) out[pb + r + 16] = oacc2 + bias2;
            if (pb + r + 24 < M) out[pb + r + 24] = oacc3 + bias2;
        }
    }
}

extern "C" void kernel_launch(void* const* d_in, const int* in_sizes, int n_in,
                              void* d_out, int out_size) {
    const float* coords = (const float*)d_in[0];
    const float* lines  = (const float*)d_in[1];
    const float* W1     = (const float*)d_in[2];
    const float* b1     = (const float*)d_in[3];
    const float* W2     = (const float*)d_in[4];
    const float* b2     = (const float*)d_in[5];
    float* out = (float*)d_out;

    int M = in_sizes[0] / 3;

    cudaFuncSetAttribute(rank1_hmma_kernel,
                         cudaFuncAttributeMaxDynamicSharedMemorySize, SMEM_BYTES);

    rank1_hmma_kernel<<<NBLOCKS, NTHREADS, SMEM_BYTES>>>(
        coords, lines, W1, b1, W2, b2, out, M);
}

// round 8
// speedup vs baseline: 7.2577x; 1.4870x over previous
#include <cuda_runtime.h>
#include <cuda_fp16.h>
#include <cstdint>

// RankOnePlanes, round 8: instruction-count attack.
// R7 showed time ~ total issue slots (issue stuck at 48% across 16 and 24
// warps/SM). Cuts: single-pass fp16 MMA (192->64 MMA, 32->16 LDSM, no split
// A-build), f32x2 packed feature math (104->52 fp ops/pt), fp16 W1 (smem
// 66.5KB, 3 CTAs/SM). Table gather layout unchanged (L1 floor ~245 wf/tile).

#define LTAB 128
#define CL 32
#define HDIM 128
#define TSTRIDE 36   // floats per table row (4 x 32B quarter-blocks + 16B pad)
#define NTHREADS 256
#define WARPS_PER_CTA 8
#define NBLOCKS 456  // 3 per SM
#define ROWPAD 80    // W1 fp16 row bytes (64B data + 16B pad; 5r mod 8 perm)

// ---- smem byte offsets ----
#define SM_TAB 0                          // 3*128*36*4 = 55296
#define SM_W1  55296                      // 128 * 80   = 10240
#define SM_B1  65536                      // 512
#define SM_W2  66048                      // 512
#define SMEM_BYTES 66560                  // x3 CTAs = 199.7 KB/SM

typedef unsigned long long ull;

__device__ __forceinline__ uint32_t smem_u32(const void* p) {
    uint32_t a;
    asm("{ .reg .u64 t; cvta.to.shared.u64 t, %1; cvt.u32.u64 %0, t; }"
        : "=r"(a) : "l"(p));
    return a;
}
__device__ __forceinline__ void ldsm_x4(uint32_t addr, uint32_t* r) {
    asm volatile("ldmatrix.sync.aligned.m8n8.x4.shared.b16 {%0,%1,%2,%3}, [%4];"
                 : "=r"(r[0]), "=r"(r[1]), "=r"(r[2]), "=r"(r[3]) : "r"(addr));
}
__device__ __forceinline__ void mma_f16(float4& c, const uint32_t* a,
                                        const uint32_t* b) {
    asm volatile(
        "mma.sync.aligned.m16n8k16.row.col.f32.f16.f16.f32 "
        "{%0,%1,%2,%3}, {%4,%5,%6,%7}, {%8,%9}, {%0,%1,%2,%3};"
        : "+f"(c.x), "+f"(c.y), "+f"(c.z), "+f"(c.w)
        : "r"(a[0]), "r"(a[1]), "r"(a[2]), "r"(a[3]), "r"(b[0]), "r"(b[1]));
}
// pack (lo, hi) floats -> f16x2 (lo in low half)
__device__ __forceinline__ uint32_t pkh(float lo, float hi) {
    uint32_t r;
    asm("cvt.rn.f16x2.f32 %0, %1, %2;" : "=r"(r) : "f"(hi), "f"(lo));
    return r;
}
// ---- f32x2 packed helpers ----
__device__ __forceinline__ ull pk2(float lo, float hi) {
    ull r;
    asm("mov.b64 %0, {%1, %2};" : "=l"(r) : "f"(lo), "f"(hi));
    return r;
}
__device__ __forceinline__ void unpk2(float& lo, float& hi, ull v) {
    asm("mov.b64 {%0, %1}, %2;" : "=f"(lo), "=f"(hi) : "l"(v));
}
__device__ __forceinline__ ull mul2(ull a, ull b) {
    ull d;
    asm("mul.rn.f32x2 %0, %1, %2;" : "=l"(d) : "l"(a), "l"(b));
    return d;
}
__device__ __forceinline__ ull add2(ull a, ull b) {
    ull d;
    asm("add.rn.f32x2 %0, %1, %2;" : "=l"(d) : "l"(a), "l"(b));
    return d;
}
__device__ __forceinline__ ull fma2(ull a, ull b, ull c) {
    ull d;
    asm("fma.rn.f32x2 %0, %1, %2, %3;" : "=l"(d) : "l"(a), "l"(b), "l"(c));
    return d;
}

__device__ __forceinline__ void sample_setup(float c, int& r0, int& r1,
                                             float& w0, float& w1) {
    float pos = (c + 1.0f) * 63.5f;
    float f0  = floorf(pos);
    float fr  = pos - f0;
    int i0 = (int)f0;
    int i1 = i0 + 1;
    w0 = ((unsigned)i0 < (unsigned)LTAB) ? (1.0f - fr) : 0.0f;
    w1 = ((unsigned)i1 < (unsigned)LTAB) ? fr : 0.0f;
    r0 = min(max(i0, 0), LTAB - 1);
    r1 = min(max(i1, 0), LTAB - 1);
}

// 8 features of one point (this lane's quarter-block channels), f32x2 math,
// emitted directly as 4 f16x2 regs.
__device__ __forceinline__ void feats8_h(const float* __restrict__ sT, int qoff,
                                         float cx, float cy, float cz,
                                         uint32_t* __restrict__ hreg) {
    int xr0, xr1, yr0, yr1, zr0, zr1;
    float xw0, xw1, yw0, yw1, zw0, zw1;
    sample_setup(cx, xr0, xr1, xw0, xw1);
    sample_setup(cy, yr0, yr1, yw0, yw1);
    sample_setup(cz, zr0, zr1, zw0, zw1);

    const ulonglong2* X0 = reinterpret_cast<const ulonglong2*>(&sT[(0 * LTAB + xr0) * TSTRIDE + qoff]);
    const ulonglong2* X1 = reinterpret_cast<const ulonglong2*>(&sT[(0 * LTAB + xr1) * TSTRIDE + qoff]);
    const ulonglong2* Y0 = reinterpret_cast<const ulonglong2*>(&sT[(1 * LTAB + yr0) * TSTRIDE + qoff]);
    const ulonglong2* Y1 = reinterpret_cast<const ulonglong2*>(&sT[(1 * LTAB + yr1) * TSTRIDE + qoff]);
    const ulonglong2* Z0 = reinterpret_cast<const ulonglong2*>(&sT[(2 * LTAB + zr0) * TSTRIDE + qoff]);
    const ulonglong2* Z1 = reinterpret_cast<const ulonglong2*>(&sT[(2 * LTAB + zr1) * TSTRIDE + qoff]);

    const ull xw0p = pk2(xw0, xw0), xw1p = pk2(xw1, xw1);
    const ull yw0p = pk2(yw0, yw0), yw1p = pk2(yw1, yw1);
    const ull zw0p = pk2(zw0, zw0), zw1p = pk2(zw1, zw1);
    const ull invRp  = 0x4020000040200000ull;  // {2.5f, 2.5f}
    const ull invR2p = 0x40C8000040C80000ull;  // {6.25f, 6.25f}

    ulonglong2 x0 = X0[0], x0b = X0[1];
    ulonglong2 x1 = X1[0], x1b = X1[1];
    ulonglong2 y0 = Y0[0], y0b = Y0[1];
    ulonglong2 y1 = Y1[0], y1b = Y1[1];
    ulonglong2 z0 = Z0[0], z0b = Z0[1];
    ulonglong2 z1 = Z1[0], z1b = Z1[1];

    ull xp[4] = {x0.x, x0.y, x0b.x, x0b.y};
    ull xq[4] = {x1.x, x1.y, x1b.x, x1b.y};
    ull yp[4] = {y0.x, y0.y, y0b.x, y0b.y};
    ull yq[4] = {y1.x, y1.y, y1b.x, y1b.y};
    ull zp[4] = {z0.x, z0.y, z0b.x, z0b.y};
    ull zq[4] = {z1.x, z1.y, z1b.x, z1b.y};

#pragma unroll
    for (int pr = 0; pr < 4; pr++) {
        ull xv = fma2(xq[pr], xw1p, mul2(xp[pr], xw0p));
        ull yv = fma2(yq[pr], yw1p, mul2(yp[pr], yw0p));
        ull zv = fma2(zq[pr], zw1p, mul2(zp[pr], zw0p));
        ull e  = add2(xv, yv);
        ull s  = add2(e, zv);
        ull xy = mul2(xv, yv);
        ull p2 = fma2(zv, e, xy);
        ull p3 = mul2(xy, zv);
        ull f  = fma2(p2, invRp, s);
        f = fma2(p3, invR2p, f);
        float flo, fhi;
        unpk2(flo, fhi, f);
        hreg[pr] = pkh(flo, fhi);
    }
}

__global__ __launch_bounds__(NTHREADS, 3)
void rank1_hmma_kernel(const float* __restrict__ coords,
                       const float* __restrict__ lines,
                       const float* __restrict__ W1,
                       const float* __restrict__ b1,
                       const float* __restrict__ W2,
                       const float* __restrict__ b2,
                       float* __restrict__ out, int M) {
    extern __shared__ char smc[];
    const uint32_t sb = smem_u32(smc);
    float* sT  = reinterpret_cast<float*>(smc + SM_TAB);
    float* sb1 = reinterpret_cast<float*>(smc + SM_B1);
    float* sW2 = reinterpret_cast<float*>(smc + SM_W2);

    const int tid  = threadIdx.x;
    const int wid  = tid >> 5;
    const int lane = tid & 31;

    // ---- stage table: per row, 4 quarter-blocks of 8 permuted channels ----
    // block q holds channels {2q,2q+1,2q+8,2q+9,2q+16,2q+17,2q+24,2q+25}
    for (int idx = tid; idx < 3 * LTAB; idx += NTHREADS) {
        const float* src = lines + idx * CL;
        float v[CL];
#pragma unroll
        for (int j = 0; j < 8; j++) {
            float4 t4 = reinterpret_cast<const float4*>(src)[j];
            v[4 * j + 0] = t4.x; v[4 * j + 1] = t4.y;
            v[4 * j + 2] = t4.z; v[4 * j + 3] = t4.w;
        }
        float* dst = sT + idx * TSTRIDE;
#pragma unroll
        for (int q = 0; q < 4; q++) {
            dst[8 * q + 0] = v[2 * q];      dst[8 * q + 1] = v[2 * q + 1];
            dst[8 * q + 2] = v[2 * q + 8];  dst[8 * q + 3] = v[2 * q + 9];
            dst[8 * q + 4] = v[2 * q + 16]; dst[8 * q + 5] = v[2 * q + 17];
            dst[8 * q + 6] = v[2 * q + 24]; dst[8 * q + 7] = v[2 * q + 25];
        }
    }
    // ---- stage b1, W2, fp16 W1 (channel order identity) ----
    if (tid < HDIM) {
        sb1[tid] = b1[tid];
        sW2[tid] = W2[tid];
        char* dst = smc + SM_W1 + tid * ROWPAD;
        const float4* wrow = reinterpret_cast<const float4*>(W1 + tid * CL);
#pragma unroll
        for (int j = 0; j < 8; j += 2) {
            float4 wa = wrow[j], wb = wrow[j + 1];
            uint4 vh = make_uint4(pkh(wa.x, wa.y), pkh(wa.z, wa.w),
                                  pkh(wb.x, wb.y), pkh(wb.z, wb.w));
            *reinterpret_cast<uint4*>(dst + j * 8) = vh;
        }
    }
    __syncthreads();

    const float bias2 = __ldg(b2);
    const uint32_t sbW1 = sb + SM_W1;

    // B ldmatrix addressing: 16 rows (2 n-tiles) x k16-chunk columns
    const uint32_t b_row = (uint32_t)((lane & 7) + ((lane & 16) ? 8 : 0));
    const uint32_t b_addr_base =
        sbW1 + b_row * ROWPAD + (uint32_t)((lane & 8) ? 16 : 0);

    const int qoff = (lane & 3) * 8;
    const int base = lane >> 2;

    const int warp_gid    = blockIdx.x * WARPS_PER_CTA + wid;
    const int total_warps = NBLOCKS * WARPS_PER_CTA;
    const int tiles       = (M + 31) >> 5;

    for (int t = warp_gid; t < tiles; t += total_warps) {
        // ---- build fp16 A fragments in registers: 4 points per lane ----
        uint32_t afr[2][2][4];   // [row-tile][k16-chunk][frag reg]
#pragma unroll
        for (int pi = 0; pi < 4; pi++) {
            int prow = base + pi * 8;
            int p  = t * 32 + prow;
            int pc = (p < M) ? p : (M - 1);
            float cx = __ldg(&coords[3 * pc + 0]);
            float cy = __ldg(&coords[3 * pc + 1]);
            float cz = __ldg(&coords[3 * pc + 2]);
            uint32_t h[4];
            feats8_h(sT, qoff, cx, cy, cz, h);

            int rt = pi >> 1;
            int rs = pi & 1;
            afr[rt][0][rs]     = h[0];   // cols 2q,2q+1       (k chunk 0)
            afr[rt][0][2 + rs] = h[1];   // cols 2q+8,2q+9
            afr[rt][1][rs]     = h[2];   // cols 2q+16,2q+17   (k chunk 1)
            afr[rt][1][2 + rs] = h[3];   // cols 2q+24,2q+25
        }

        float oacc0 = 0.0f, oacc1 = 0.0f, oacc2 = 0.0f, oacc3 = 0.0f;
        const int colb = (lane & 3) * 2;

#pragma unroll
        for (int np = 0; np < 8; np++) {
            uint32_t b[2][4];  // [k16 chunk][ntile0 b0,b1, ntile1 b0,b1]
            uint32_t nb = b_addr_base + (uint32_t)(np * 16) * ROWPAD;
            ldsm_x4(nb,      b[0]);
            ldsm_x4(nb + 32, b[1]);

            float4 c[2][2];
#pragma unroll
            for (int rt = 0; rt < 2; rt++)
#pragma unroll
                for (int nt = 0; nt < 2; nt++) {
                    c[rt][nt] = make_float4(0.f, 0.f, 0.f, 0.f);
                    mma_f16(c[rt][nt], afr[rt][0], &b[0][nt * 2]);
                    mma_f16(c[rt][nt], afr[rt][1], &b[1][nt * 2]);
                }

            // ---- fused epilogue on fragments ----
            int col0 = np * 16 + colb;
            float2 b1a = *reinterpret_cast<const float2*>(&sb1[col0]);
            float2 w2a = *reinterpret_cast<const float2*>(&sW2[col0]);
            float2 b1b = *reinterpret_cast<const float2*>(&sb1[col0 + 8]);
            float2 w2b = *reinterpret_cast<const float2*>(&sW2[col0 + 8]);
#pragma unroll
            for (int rt = 0; rt < 2; rt++) {
                float lo = 0.0f, hi = 0.0f;
                lo = fmaf(fmaxf(c[rt][0].x + b1a.x, 0.f), w2a.x, lo);
                lo = fmaf(fmaxf(c[rt][0].y + b1a.y, 0.f), w2a.y, lo);
                lo = fmaf(fmaxf(c[rt][1].x + b1b.x, 0.f), w2b.x, lo);
                lo = fmaf(fmaxf(c[rt][1].y + b1b.y, 0.f), w2b.y, lo);
                hi = fmaf(fmaxf(c[rt][0].z + b1a.x, 0.f), w2a.x, hi);
                hi = fmaf(fmaxf(c[rt][0].w + b1a.y, 0.f), w2a.y, hi);
                hi = fmaf(fmaxf(c[rt][1].z + b1b.x, 0.f), w2b.x, hi);
                hi = fmaf(fmaxf(c[rt][1].w + b1b.y, 0.f), w2b.y, hi);
                if (rt == 0) { oacc0 += lo; oacc1 += hi; }
                else         { oacc2 += lo; oacc3 += hi; }
            }
        }

        // ---- reduce over the 4 lanes sharing each row ----
        oacc0 += __shfl_xor_sync(0xffffffffu, oacc0, 1);
        oacc0 += __shfl_xor_sync(0xffffffffu, oacc0, 2);
        oacc1 += __shfl_xor_sync(0xffffffffu, oacc1, 1);
        oacc1 += __shfl_xor_sync(0xffffffffu, oacc1, 2);
        oacc2 += __shfl_xor_sync(0xffffffffu, oacc2, 1);
        oacc2 += __shfl_xor_sync(0xffffffffu, oacc2, 2);
        oacc3 += __shfl_xor_sync(0xffffffffu, oacc3, 1);
        oacc3 += __shfl_xor_sync(0xffffffffu, oacc3, 2);

        if ((lane & 3) == 0) {
            int r  = lane >> 2;
            int pb = t * 32;
            if (pb + r      < M) out[pb + r]      = oacc0 + bias2;
            if (pb + r + 8  < M) out[pb + r + 8]  = oacc1 + bias2;
            if (pb + r + 16 < M) out[pb + r + 16] = oacc2 + bias2;
            if (pb + r + 24 < M) out[pb + r + 24] = oacc3 + bias2;
        }
    }
}

extern "C" void kernel_launch(void* const* d_in, const int* in_sizes, int n_in,
                              void* d_out, int out_size) {
    const float* coords = (const float*)d_in[0];
    const float* lines  = (const float*)d_in[1];
    const float* W1     = (const float*)d_in[2];
    const float* b1     = (const float*)d_in[3];
    const float* W2     = (const float*)d_in[4];
    const float* b2     = (const float*)d_in[5];
    float* out = (float*)d_out;

    int M = in_sizes[0] / 3;

    cudaFuncSetAttribute(rank1_hmma_kernel,
                         cudaFuncAttributeMaxDynamicSharedMemorySize, SMEM_BYTES);

    rank1_hmma_kernel<<<NBLOCKS, NTHREADS, SMEM_BYTES>>>(
        coords, lines, W1, b1, W2, b2, out, M);
}